// round 16
// baseline (speedup 1.0000x reference)
#include <cuda_runtime.h>
#include <cuda_bf16.h>
#include <math.h>
#include <cstdint>

// Problem constants (GCNAggregator): B=4096, K=32, U=32768, V=100000, D=128
#define GCN_B 4096
#define GCN_K 32
#define GCN_U 32768
#define GCN_D 128
#define AGG_WARPS 4      // rows (warps) per aggregate block -> 1024 blocks

// Scratch (no cudaMalloc allowed)
__device__ int  g_col_deg[GCN_U];
__device__ int2 g_oc[GCN_B * GCN_K];   // per edge: {off4, c | (first << 31)}

// ---------------------------------------------------------------------------
// Kernel 1: per-row dedupe + degree accumulation + edge precompute.
// Ends with griddepcontrol.launch_dependents: the aggregate kernel (launched
// with ProgrammaticStreamSerialization) may begin scheduling while this grid
// drains; its griddepcontrol.wait guarantees our stores are visible.
// ---------------------------------------------------------------------------
__global__ void dedupe_degree_kernel(const int* __restrict__ neigh_cols,
                                     const int* __restrict__ unique_ids) {
    int warp_in_block = threadIdx.x >> 5;
    int lane = threadIdx.x & 31;
    int b = blockIdx.x * (blockDim.x >> 5) + warp_in_block;
    int e = b * GCN_K + lane;

    int c = neigh_cols[e];
    int off4 = __ldg(&unique_ids[c]) * (GCN_D / 4);   // independent -> hidden

    unsigned peers = __match_any_sync(0xFFFFFFFFu, c);
    bool first = ((int)__ffs(peers) - 1) == lane;     // lowest lane holding c
    if (first) atomicAdd(&g_col_deg[c], 1);           // spread addresses -> cheap

    g_oc[e] = make_int2(off4, c | (first ? 0x80000000 : 0));

    // Allow the dependent (aggregate) grid to start launching.
    asm volatile("griddepcontrol.launch_dependents;");
}

// ---------------------------------------------------------------------------
// Kernel 2: aggregation (champion R15 structure). One warp per row; lane owns
// 4 consecutive dims (LDG.128 via __ldcg). Prologue is a single LDG.64 of the
// precomputed (off4, flagged c); gathers launch after ONE memory epoch; the
// weight chain resolves under the in-flight gathers. Duplicates carry w=0.
// Launched with PDL: griddepcontrol.wait before any dependent read.
// ---------------------------------------------------------------------------
__global__ void __launch_bounds__(32 * AGG_WARPS)
aggregate_kernel(const float4* __restrict__ embed_table4,  // [V, 32] float4
                 float4* __restrict__ out4) {              // [B, 32] float4
    const int warp = threadIdx.x >> 5;
    const int lane = threadIdx.x & 31;
    const int b    = blockIdx.x * AGG_WARPS + warp;

    __shared__ int2 s_wo[AGG_WARPS][GCN_K];   // {off4, bitcast(w)}

    // Wait for the dedupe grid's stores (g_oc, g_col_deg) to be visible.
    asm volatile("griddepcontrol.wait;" ::: "memory");

    // ---- step 1: ONE load resolves everything needed to start gathering ----
    const int2 oc = __ldcg(&g_oc[b * GCN_K + lane]);
    s_wo[warp][lane].x = oc.x;
    __syncwarp();

    // ---- step 2: launch the gather pipeline immediately ----
    constexpr int P = 8;
    float4 buf[P];
    #pragma unroll
    for (int i = 0; i < P; i++)
        buf[i] = __ldcg(&embed_table4[s_wo[warp][i].x + lane]);

    // ---- step 3: weight chain resolves under the in-flight gathers ----
    const bool first = oc.y < 0;
    const unsigned mask = __ballot_sync(0xFFFFFFFFu, first);
    float w = 0.0f;
    if (first) {
        int deg = __ldcg(&g_col_deg[oc.y & 0x7FFFFFFF]);  // >= 1 here
        w = rsqrtf((float)deg);
    }
    w *= rsqrtf((float)__popc(mask));         // fold row scale into lane weight
    s_wo[warp][lane].y = __float_as_int(w);
    __syncwarp();

    // ---- step 4: rolling FMA + refill ----
    float4 acc = make_float4(0.f, 0.f, 0.f, 0.f);
    #pragma unroll
    for (int k = 0; k < GCN_K; k++) {
        int2  wo = s_wo[warp][k];
        float wk = __int_as_float(wo.y);
        float4 v = buf[k & (P - 1)];
        acc.x = fmaf(wk, v.x, acc.x);
        acc.y = fmaf(wk, v.y, acc.y);
        acc.z = fmaf(wk, v.z, acc.z);
        acc.w = fmaf(wk, v.w, acc.w);
        if (k + P < GCN_K)
            buf[k & (P - 1)] = __ldcg(&embed_table4[s_wo[warp][k + P].x + lane]);
    }

    out4[b * (GCN_D / 4) + lane] = acc;
}

// ---------------------------------------------------------------------------
extern "C" void kernel_launch(void* const* d_in, const int* in_sizes, int n_in,
                              void* d_out, int out_size) {
    const int*    neigh_cols   = (const int*)d_in[0];
    const int*    unique_ids   = (const int*)d_in[1];
    const float4* embed_table4 = (const float4*)d_in[2];
    float4*       out4         = (float4*)d_out;

    // Zero column degrees via a graph memset node (no dedicated kernel launch).
    void* col_deg_ptr = nullptr;
    cudaGetSymbolAddress(&col_deg_ptr, g_col_deg);
    cudaMemsetAsync(col_deg_ptr, 0, GCN_U * sizeof(int));

    dedupe_degree_kernel<<<GCN_B / 8, 256>>>(neigh_cols, unique_ids);

    // Aggregate launched with Programmatic Dependent Launch: it may begin
    // scheduling while dedupe drains; griddepcontrol.wait enforces the data
    // dependency inside the kernel.
    cudaLaunchConfig_t cfg = {};
    cfg.gridDim  = dim3(GCN_B / AGG_WARPS);
    cfg.blockDim = dim3(32 * AGG_WARPS);
    cudaLaunchAttribute attrs[1];
    attrs[0].id = cudaLaunchAttributeProgrammaticStreamSerialization;
    attrs[0].val.programmaticStreamSerializationAllowed = 1;
    cfg.attrs = attrs;
    cfg.numAttrs = 1;
    cudaLaunchKernelEx(&cfg, aggregate_kernel, embed_table4, out4);
}

// round 17
// speedup vs baseline: 1.0151x; 1.0151x over previous
#include <cuda_runtime.h>
#include <cuda_bf16.h>
#include <math.h>
#include <cstdint>

// Problem constants (GCNAggregator): B=4096, K=32, U=32768, V=100000, D=128
#define GCN_B 4096
#define GCN_K 32
#define GCN_U 32768
#define GCN_D 128
#define AGG_WARPS 4      // rows (warps) per aggregate block -> 1024 blocks

// Scratch (no cudaMalloc allowed).
// INVARIANT: g_col_deg is all-zero at every kernel_launch entry (zero-init at
// load; re-zeroed by col_weight_kernel each replay).
__device__ int   g_col_deg[GCN_U];
__device__ float g_col_w[GCN_U];
__device__ int2  g_oc[GCN_B * GCN_K];   // per edge: {off4, c | (first << 31)}

// ---------------------------------------------------------------------------
// Kernel 1: per-row dedupe + degree accumulation + edge precompute.
// ---------------------------------------------------------------------------
__global__ void dedupe_degree_kernel(const int* __restrict__ neigh_cols,
                                     const int* __restrict__ unique_ids) {
    int warp_in_block = threadIdx.x >> 5;
    int lane = threadIdx.x & 31;
    int b = blockIdx.x * (blockDim.x >> 5) + warp_in_block;
    int e = b * GCN_K + lane;

    int c = neigh_cols[e];
    int off4 = __ldg(&unique_ids[c]) * (GCN_D / 4);   // independent -> hidden

    unsigned peers = __match_any_sync(0xFFFFFFFFu, c);
    bool first = ((int)__ffs(peers) - 1) == lane;     // lowest lane holding c
    if (first) atomicAdd(&g_col_deg[c], 1);           // spread addresses -> cheap

    g_oc[e] = make_int2(off4, c | (first ? 0x80000000 : 0));

    asm volatile("griddepcontrol.launch_dependents;");
}

// ---------------------------------------------------------------------------
// Kernel 2: column weights. Reads final degree, publishes col_w = rsqrt(deg),
// and RE-ZEROES col_deg (restores the replay invariant -> no memset node).
// ---------------------------------------------------------------------------
__global__ void col_weight_kernel() {
    asm volatile("griddepcontrol.wait;" ::: "memory");  // all degree atomics done
    int u = blockIdx.x * blockDim.x + threadIdx.x;
    int deg = g_col_deg[u];
    g_col_w[u] = (deg > 0) ? rsqrtf((float)deg) : 0.0f;
    g_col_deg[u] = 0;
    asm volatile("griddepcontrol.launch_dependents;");
}

// ---------------------------------------------------------------------------
// Kernel 3: aggregation (champion structure). One warp per row; lane owns 4
// consecutive dims (LDG.128 via __ldcg). Prologue = one LDG.64 of (off4,
// flagged c); gathers launch after one memory epoch; the (now shortened)
// weight chain -- a single float load + mul -- resolves under the in-flight
// gathers. Duplicates carry w=0 -> branch-free.
// ---------------------------------------------------------------------------
__global__ void __launch_bounds__(32 * AGG_WARPS)
aggregate_kernel(const float4* __restrict__ embed_table4,  // [V, 32] float4
                 float4* __restrict__ out4) {              // [B, 32] float4
    const int warp = threadIdx.x >> 5;
    const int lane = threadIdx.x & 31;
    const int b    = blockIdx.x * AGG_WARPS + warp;

    __shared__ int2 s_wo[AGG_WARPS][GCN_K];   // {off4, bitcast(w)}

    asm volatile("griddepcontrol.wait;" ::: "memory");  // col_w + g_oc visible

    // ---- step 1: ONE load resolves everything needed to start gathering ----
    const int2 oc = __ldcg(&g_oc[b * GCN_K + lane]);
    s_wo[warp][lane].x = oc.x;
    __syncwarp();

    // ---- step 2: launch the gather pipeline immediately ----
    constexpr int P = 8;
    float4 buf[P];
    #pragma unroll
    for (int i = 0; i < P; i++)
        buf[i] = __ldcg(&embed_table4[s_wo[warp][i].x + lane]);

    // ---- step 3: shortened weight chain under the in-flight gathers ----
    const bool first = oc.y < 0;
    const unsigned mask = __ballot_sync(0xFFFFFFFFu, first);
    float w = first ? __ldcg(&g_col_w[oc.y & 0x7FFFFFFF]) : 0.0f;
    w *= rsqrtf((float)__popc(mask));         // fold row scale into lane weight
    s_wo[warp][lane].y = __float_as_int(w);
    __syncwarp();

    // ---- step 4: rolling FMA + refill ----
    float4 acc = make_float4(0.f, 0.f, 0.f, 0.f);
    #pragma unroll
    for (int k = 0; k < GCN_K; k++) {
        int2  wo = s_wo[warp][k];
        float wk = __int_as_float(wo.y);
        float4 v = buf[k & (P - 1)];
        acc.x = fmaf(wk, v.x, acc.x);
        acc.y = fmaf(wk, v.y, acc.y);
        acc.z = fmaf(wk, v.z, acc.z);
        acc.w = fmaf(wk, v.w, acc.w);
        if (k + P < GCN_K)
            buf[k & (P - 1)] = __ldcg(&embed_table4[s_wo[warp][k + P].x + lane]);
    }

    out4[b * (GCN_D / 4) + lane] = acc;
}

// ---------------------------------------------------------------------------
extern "C" void kernel_launch(void* const* d_in, const int* in_sizes, int n_in,
                              void* d_out, int out_size) {
    const int*    neigh_cols   = (const int*)d_in[0];
    const int*    unique_ids   = (const int*)d_in[1];
    const float4* embed_table4 = (const float4*)d_in[2];
    float4*       out4         = (float4*)d_out;

    // No memset node: col_weight_kernel restores the col_deg == 0 invariant.
    dedupe_degree_kernel<<<GCN_B / 8, 256>>>(neigh_cols, unique_ids);

    cudaLaunchAttribute attrs[1];
    attrs[0].id = cudaLaunchAttributeProgrammaticStreamSerialization;
    attrs[0].val.programmaticStreamSerializationAllowed = 1;

    cudaLaunchConfig_t cfg1 = {};
    cfg1.gridDim  = dim3(GCN_U / 256);
    cfg1.blockDim = dim3(256);
    cfg1.attrs = attrs;
    cfg1.numAttrs = 1;
    cudaLaunchKernelEx(&cfg1, col_weight_kernel);

    cudaLaunchConfig_t cfg2 = {};
    cfg2.gridDim  = dim3(GCN_B / AGG_WARPS);
    cfg2.blockDim = dim3(32 * AGG_WARPS);
    cfg2.attrs = attrs;
    cfg2.numAttrs = 1;
    cudaLaunchKernelEx(&cfg2, aggregate_kernel, embed_table4, out4);
}